// round 15
// baseline (speedup 1.0000x reference)
#include <cuda_runtime.h>
#include <cuda_fp16.h>

#define U_N   100000
#define I_N   50000
#define NUI   150000
#define KDIM  64
#define E_II  1600000
#define E_UI  4800000
#define EPS_F 1e-12f
#define SLOTS 128           // fixed bucket capacity per destination (deg ~ Poisson(32))

// ---------------- static device scratch (allocation-free) ----------------
// bucket entries hold (src*8, weight-bits): src pre-scaled to float4-row base.
__device__ int2  g_ui_bkt[(long long)NUI * SLOTS];   // 153.6 MB
__device__ int2  g_ii_bkt[(long long)I_N * SLOTS];   //  51.2 MB
__device__ int   g_ui_cnt[NUI];
__device__ int   g_ii_cnt[I_N];

// fp16 propagation buffers; float4-typed for 16B alignment. Row = 128B = 8 float4.
__device__ float4 g_eh0[NUI * 8];
__device__ float4 g_eh1[NUI * 8];
__device__ float4 g_gh0[I_N * 8];
__device__ float4 g_gh1[I_N * 8];

// ---------------- fused init + single-pass bucketed fill -------------------
__global__ void __launch_bounds__(256) k_build(const float* __restrict__ Gu,
                                               const float* __restrict__ Gi,
                                               const float* __restrict__ Gis,
                                               const int* __restrict__ ui_src,
                                               const int* __restrict__ ui_dst,
                                               const float* __restrict__ ui_w,
                                               const int* __restrict__ ii_src,
                                               const int* __restrict__ ii_dst,
                                               const float* __restrict__ ii_w) {
    const int stride  = gridDim.x * blockDim.x;
    const int stride4 = stride * 4;
    int gtid = blockIdx.x * blockDim.x + threadIdx.x;

    // zero bucket counters (must complete before this thread's atomics touch
    // them? No — counters are zeroed by SAME kernel but possibly OTHER blocks.
    // So counters are zeroed in a prior tiny kernel instead. Here: fp16 init.)

    // fp16 init (vectorized float4 -> 2x half2)
    const int n1  = NUI * 16;          // float4 elements of ego
    const int nGu = U_N * 16;
    const int tot = n1 + I_N * 16;
    for (int i = gtid; i < tot; i += stride) {
        float4 v;
        __half2* dst;
        if (i < n1) {
            v = (i < nGu) ? __ldcs(&((const float4*)Gu)[i])
                          : __ldcs(&((const float4*)Gi)[i - nGu]);
            dst = (__half2*)g_eh0 + (size_t)i * 2;
        } else {
            v = __ldcs(&((const float4*)Gis)[i - n1]);
            dst = (__half2*)g_gh0 + (size_t)(i - n1) * 2;
        }
        __half2 h0 = __float22half2_rn(make_float2(v.x, v.y));
        __half2 h1 = __float22half2_rn(make_float2(v.z, v.w));
        *(uint2*)dst = make_uint2(*(unsigned*)&h0, *(unsigned*)&h1);
    }

    // bucketed fill (src pre-scaled by 8 = row base in float4 units)
    for (int e = gtid * 4; e < E_UI; e += stride4) {
        int4   d  = __ldcs((const int4*)(ui_dst + e));
        int4   sr = __ldcs((const int4*)(ui_src + e));
        float4 wv = __ldcs((const float4*)(ui_w + e));
        int p;
        p = atomicAdd(&g_ui_cnt[d.x], 1);
        if (p < SLOTS) g_ui_bkt[(size_t)d.x * SLOTS + p] = make_int2(sr.x * 8, __float_as_int(wv.x));
        p = atomicAdd(&g_ui_cnt[d.y], 1);
        if (p < SLOTS) g_ui_bkt[(size_t)d.y * SLOTS + p] = make_int2(sr.y * 8, __float_as_int(wv.y));
        p = atomicAdd(&g_ui_cnt[d.z], 1);
        if (p < SLOTS) g_ui_bkt[(size_t)d.z * SLOTS + p] = make_int2(sr.z * 8, __float_as_int(wv.z));
        p = atomicAdd(&g_ui_cnt[d.w], 1);
        if (p < SLOTS) g_ui_bkt[(size_t)d.w * SLOTS + p] = make_int2(sr.w * 8, __float_as_int(wv.w));
        if (e < E_II) {
            int4   d2  = __ldcs((const int4*)(ii_dst + e));
            int4   sr2 = __ldcs((const int4*)(ii_src + e));
            float4 wv2 = __ldcs((const float4*)(ii_w + e));
            p = atomicAdd(&g_ii_cnt[d2.x], 1);
            if (p < SLOTS) g_ii_bkt[(size_t)d2.x * SLOTS + p] = make_int2(sr2.x * 8, __float_as_int(wv2.x));
            p = atomicAdd(&g_ii_cnt[d2.y], 1);
            if (p < SLOTS) g_ii_bkt[(size_t)d2.y * SLOTS + p] = make_int2(sr2.y * 8, __float_as_int(wv2.y));
            p = atomicAdd(&g_ii_cnt[d2.z], 1);
            if (p < SLOTS) g_ii_bkt[(size_t)d2.z * SLOTS + p] = make_int2(sr2.z * 8, __float_as_int(wv2.z));
            p = atomicAdd(&g_ii_cnt[d2.w], 1);
            if (p < SLOTS) g_ii_bkt[(size_t)d2.w * SLOTS + p] = make_int2(sr2.w * 8, __float_as_int(wv2.w));
        }
    }
}

// tiny counter-zero kernel (must precede k_build's atomics)
__global__ void k_zero() {
    int i = blockIdx.x * blockDim.x + threadIdx.x;
    if (i < NUI) g_ui_cnt[i] = 0;
    if (i < I_N) g_ii_cnt[i] = 0;
}

// ---------------- gather core (R8 loop; 32-bit pre-scaled addressing) ------
// 4 edge-slots x 8 lanes, 16-edge pipeline, 4 gathers in flight.
__device__ __forceinline__ void gather_row(const int* __restrict__ cnt,
                                           const int2* __restrict__ bkt,
                                           const float4* __restrict__ x,
                                           int row, int slot, int sub,
                                           float a[8]) {
    int beg = row * SLOTS;
    int n   = cnt[row];
    if (n > SLOTS) n = SLOTS;
    int end = beg + n;
    #pragma unroll
    for (int k = 0; k < 8; k++) a[k] = 0.f;

    int2 ed[4];
    #pragma unroll
    for (int g = 0; g < 4; g++) {
        int i = beg + 4 * g + slot;
        ed[g] = (i < end) ? __ldg(&bkt[i]) : make_int2(0, 0);
    }

    int e = beg;
    for (; e + 16 <= end; e += 16) {
        int2 nx[4];
        #pragma unroll
        for (int g = 0; g < 4; g++) {
            int i = e + 16 + 4 * g + slot;
            nx[g] = (i < end) ? __ldg(&bkt[i]) : make_int2(0, 0);
        }
        float4 r[4];
        #pragma unroll
        for (int g = 0; g < 4; g++)
            r[g] = __ldg(&x[(unsigned)(ed[g].x + sub)]);   // 32-bit add only
        #pragma unroll
        for (int g = 0; g < 4; g++) {
            float w = __int_as_float(ed[g].y);
            const __half2* h = (const __half2*)&r[g];
            #pragma unroll
            for (int k = 0; k < 4; k++) {
                float2 f = __half22float2(h[k]);
                a[2 * k]     = fmaf(w, f.x, a[2 * k]);
                a[2 * k + 1] = fmaf(w, f.y, a[2 * k + 1]);
            }
        }
        #pragma unroll
        for (int g = 0; g < 4; g++) ed[g] = nx[g];
    }

    #pragma unroll
    for (int g = 0; g < 4; g++) {
        if (e + 4 * g < end) {
            float4 r = __ldg(&x[(unsigned)(ed[g].x + sub)]);
            float w = __int_as_float(ed[g].y);
            const __half2* h = (const __half2*)&r;
            #pragma unroll
            for (int k = 0; k < 4; k++) {
                float2 f = __half22float2(h[k]);
                a[2 * k]     = fmaf(w, f.x, a[2 * k]);
                a[2 * k + 1] = fmaf(w, f.y, a[2 * k + 1]);
            }
        }
    }

    #pragma unroll
    for (int k = 0; k < 8; k++) {
        a[k] += __shfl_xor_sync(0xffffffffu, a[k], 8);
        a[k] += __shfl_xor_sync(0xffffffffu, a[k], 16);
    }
}

// ---------------- SpMM passes ----------------
template <bool NORM, bool WX, bool FINAL>
__global__ void __launch_bounds__(256) k_spmm(int gsel, int xsel, int ysel,
                                              float* out,
                                              const float* __restrict__ Gu,
                                              const float* __restrict__ Gi,
                                              int nrows) {
    int row = blockIdx.x * 8 + (threadIdx.x >> 5);
    if (row >= nrows) return;
    int lane = threadIdx.x & 31;
    int slot = lane >> 3;
    int sub  = lane & 7;

    const int*  cnt = gsel ? g_ii_cnt : g_ui_cnt;
    const int2* bkt = gsel ? g_ii_bkt : g_ui_bkt;
    const float4* x = (xsel == 0) ? g_eh0 : (xsel == 1) ? g_eh1
                    : (xsel == 2) ? g_gh0 : g_gh1;
    float4* y = (ysel == 0) ? g_eh0 : (ysel == 1) ? g_eh1
              : (ysel == 2) ? g_gh0 : g_gh1;

    float a[8];
    gather_row(cnt, bkt, x, row, slot, sub, a);

    if (NORM) {
        float ssum = 0.f;
        #pragma unroll
        for (int k = 0; k < 8; k++) ssum = fmaf(a[k], a[k], ssum);
        #pragma unroll
        for (int o = 4; o; o >>= 1) ssum += __shfl_xor_sync(0xffffffffu, ssum, o);
        float scale = 1.f / fmaxf(sqrtf(ssum), EPS_F);
        #pragma unroll
        for (int k = 0; k < 8; k++) a[k] *= scale;
    }

    if (WX && slot == 0) {
        __half2 hp[4];
        #pragma unroll
        for (int k = 0; k < 4; k++)
            hp[k] = __float22half2_rn(make_float2(a[2 * k], a[2 * k + 1]));
        y[(size_t)row * 8 + sub] = *(const float4*)hp;
    }

    if (FINAL && slot < 2) {
        size_t p = (size_t)row * 16 + 2 * sub + slot;
        float4 o = (row < U_N) ? ((const float4*)Gu)[p]
                               : ((const float4*)Gi)[(size_t)(row - U_N) * 16 + 2 * sub + slot];
        float2 p1 = ((const float2*)g_eh1)[p];
        float2 p2 = ((const float2*)g_eh0)[p];
        const __half2* h1 = (const __half2*)&p1;
        const __half2* h2 = (const __half2*)&p2;
        float2 n1a = __half22float2(h1[0]), n1b = __half22float2(h1[1]);
        float2 n2a = __half22float2(h2[0]), n2b = __half22float2(h2[1]);
        o.x = 0.25f * (o.x + n1a.x + n2a.x + a[4 * slot + 0]);
        o.y = 0.25f * (o.y + n1a.y + n2a.y + a[4 * slot + 1]);
        o.z = 0.25f * (o.z + n1b.x + n2b.x + a[4 * slot + 2]);
        o.w = 0.25f * (o.w + n1b.y + n2b.y + a[4 * slot + 3]);
        if (row >= U_N) {
            float2 gp = ((const float2*)g_gh0)[(size_t)(row - U_N) * 16 + 2 * sub + slot];
            const __half2* gh = (const __half2*)&gp;
            float2 f0 = __half22float2(gh[0]);
            float2 f1 = __half22float2(gh[1]);
            float ssum = f0.x * f0.x + f0.y * f0.y + f1.x * f1.x + f1.y * f1.y;
            #pragma unroll
            for (int o2 = 8; o2; o2 >>= 1)
                ssum += __shfl_xor_sync(0xffffffffu, ssum, o2);
            float sc = 1.f / fmaxf(sqrtf(ssum), EPS_F);
            o.x = fmaf(f0.x, sc, o.x);
            o.y = fmaf(f0.y, sc, o.y);
            o.z = fmaf(f1.x, sc, o.z);
            o.w = fmaf(f1.y, sc, o.w);
        }
        ((float4*)out)[p] = o;
    }
}

// ---------------- launch ----------------
extern "C" void kernel_launch(void* const* d_in, const int* in_sizes, int n_in,
                              void* d_out, int out_size) {
    const float* Gu     = (const float*)d_in[0];
    const float* Gi     = (const float*)d_in[1];
    const float* Gis    = (const float*)d_in[2];
    const float* ii_w   = (const float*)d_in[3];
    const float* ui_w   = (const float*)d_in[4];
    const int*   ii_src = (const int*)d_in[5];
    const int*   ii_dst = (const int*)d_in[6];
    const int*   ui_src = (const int*)d_in[7];
    const int*   ui_dst = (const int*)d_in[8];
    float* out = (float*)d_out;

    k_zero<<<(NUI + 255) / 256, 256>>>();
    k_build<<<4096, 256>>>(Gu, Gi, Gis, ui_src, ui_dst, ui_w, ii_src, ii_dst, ii_w);

    int blk_ii = (I_N + 7) / 8;
    int blk_ui = (NUI + 7) / 8;

    // Item-item chain: gh1 = spmm(gh0); gh0 = spmm(gh1)
    k_spmm<false, true, false><<<blk_ii, 256>>>(1, 2, 3, nullptr, nullptr, nullptr, I_N);
    k_spmm<false, true, false><<<blk_ii, 256>>>(1, 3, 2, nullptr, nullptr, nullptr, I_N);

    // User-item chain (acc-free):
    k_spmm<true, true, false><<<blk_ui, 256>>>(0, 0, 1, nullptr, nullptr, nullptr, NUI);
    k_spmm<true, true, false><<<blk_ui, 256>>>(0, 1, 0, nullptr, nullptr, nullptr, NUI);
    k_spmm<true, false, true><<<blk_ui, 256>>>(0, 0, 1, out, Gu, Gi, NUI);
}

// round 16
// speedup vs baseline: 1.0045x; 1.0045x over previous
#include <cuda_runtime.h>
#include <cuda_fp16.h>

#define U_N   100000
#define I_N   50000
#define NUI   150000
#define KDIM  64
#define E_II  1600000
#define E_UI  4800000
#define EPS_F 1e-12f
#define SLOTS 128           // fixed bucket capacity per destination (deg ~ Poisson(32))

// ---------------- static device scratch (allocation-free) ----------------
__device__ int2  g_ui_bkt[(long long)NUI * SLOTS];   // 153.6 MB
__device__ int2  g_ii_bkt[(long long)I_N * SLOTS];   //  51.2 MB
__device__ int   g_ui_cnt[NUI];
__device__ int   g_ii_cnt[I_N];

// fp16 propagation buffers; float4-typed for 16B alignment. Row = 128B = 8 float4.
__device__ float4 g_eh0[NUI * 8];
__device__ float4 g_eh1[NUI * 8];
__device__ float4 g_gh0[I_N * 8];
__device__ float4 g_gh1[I_N * 8];

// ---------------- init: zero counters + fp16 copies of ego / Gis -----------
__global__ void __launch_bounds__(256) k_init(const float* __restrict__ Gu,
                                              const float* __restrict__ Gi,
                                              const float* __restrict__ Gis) {
    const int stride = gridDim.x * blockDim.x;
    int gtid = blockIdx.x * blockDim.x + threadIdx.x;

    for (int i = gtid; i < NUI; i += stride) {
        g_ui_cnt[i] = 0;
        if (i < I_N) g_ii_cnt[i] = 0;
    }

    const int n1  = NUI * 16;          // float4 elements of ego
    const int nGu = U_N * 16;
    const int tot = n1 + I_N * 16;
    for (int i = gtid; i < tot; i += stride) {
        float4 v;
        __half2* dst;
        if (i < n1) {
            v = (i < nGu) ? __ldcs(&((const float4*)Gu)[i])
                          : __ldcs(&((const float4*)Gi)[i - nGu]);
            dst = (__half2*)g_eh0 + (size_t)i * 2;
        } else {
            v = __ldcs(&((const float4*)Gis)[i - n1]);
            dst = (__half2*)g_gh0 + (size_t)(i - n1) * 2;
        }
        __half2 h0 = __float22half2_rn(make_float2(v.x, v.y));
        __half2 h1 = __float22half2_rn(make_float2(v.z, v.w));
        *(uint2*)dst = make_uint2(*(unsigned*)&h0, *(unsigned*)&h1);
    }
}

// ---------------- single-pass bucketed fill (no count, no scan) ------------
__global__ void __launch_bounds__(256) k_fill(const int* __restrict__ ui_src,
                                              const int* __restrict__ ui_dst,
                                              const float* __restrict__ ui_w,
                                              const int* __restrict__ ii_src,
                                              const int* __restrict__ ii_dst,
                                              const float* __restrict__ ii_w) {
    const int stride4 = gridDim.x * blockDim.x * 4;
    int e0 = (blockIdx.x * blockDim.x + threadIdx.x) * 4;

    for (int e = e0; e < E_UI; e += stride4) {
        int4   d  = __ldcs((const int4*)(ui_dst + e));
        int4   sr = __ldcs((const int4*)(ui_src + e));
        float4 wv = __ldcs((const float4*)(ui_w + e));
        int p;
        p = atomicAdd(&g_ui_cnt[d.x], 1);
        if (p < SLOTS) g_ui_bkt[(size_t)d.x * SLOTS + p] = make_int2(sr.x, __float_as_int(wv.x));
        p = atomicAdd(&g_ui_cnt[d.y], 1);
        if (p < SLOTS) g_ui_bkt[(size_t)d.y * SLOTS + p] = make_int2(sr.y, __float_as_int(wv.y));
        p = atomicAdd(&g_ui_cnt[d.z], 1);
        if (p < SLOTS) g_ui_bkt[(size_t)d.z * SLOTS + p] = make_int2(sr.z, __float_as_int(wv.z));
        p = atomicAdd(&g_ui_cnt[d.w], 1);
        if (p < SLOTS) g_ui_bkt[(size_t)d.w * SLOTS + p] = make_int2(sr.w, __float_as_int(wv.w));
        if (e < E_II) {
            int4   d2  = __ldcs((const int4*)(ii_dst + e));
            int4   sr2 = __ldcs((const int4*)(ii_src + e));
            float4 wv2 = __ldcs((const float4*)(ii_w + e));
            p = atomicAdd(&g_ii_cnt[d2.x], 1);
            if (p < SLOTS) g_ii_bkt[(size_t)d2.x * SLOTS + p] = make_int2(sr2.x, __float_as_int(wv2.x));
            p = atomicAdd(&g_ii_cnt[d2.y], 1);
            if (p < SLOTS) g_ii_bkt[(size_t)d2.y * SLOTS + p] = make_int2(sr2.y, __float_as_int(wv2.y));
            p = atomicAdd(&g_ii_cnt[d2.z], 1);
            if (p < SLOTS) g_ii_bkt[(size_t)d2.z * SLOTS + p] = make_int2(sr2.z, __float_as_int(wv2.z));
            p = atomicAdd(&g_ii_cnt[d2.w], 1);
            if (p < SLOTS) g_ii_bkt[(size_t)d2.w * SLOTS + p] = make_int2(sr2.w, __float_as_int(wv2.w));
        }
    }
}

// ---------------- gather core (exact R14/R8 loop) ------
// 4 edge-slots x 8 lanes, 16-edge pipeline, 4 gathers in flight.
__device__ __forceinline__ void gather_row(const int* __restrict__ cnt,
                                           const int2* __restrict__ bkt,
                                           const float4* __restrict__ x,
                                           int row, int slot, int sub,
                                           float a[8]) {
    int beg = row * SLOTS;
    int n   = cnt[row];
    if (n > SLOTS) n = SLOTS;
    int end = beg + n;
    #pragma unroll
    for (int k = 0; k < 8; k++) a[k] = 0.f;

    int2 ed[4];
    #pragma unroll
    for (int g = 0; g < 4; g++) {
        int i = beg + 4 * g + slot;
        ed[g] = (i < end) ? __ldg(&bkt[i]) : make_int2(0, 0);
    }

    int e = beg;
    for (; e + 16 <= end; e += 16) {
        int2 nx[4];
        #pragma unroll
        for (int g = 0; g < 4; g++) {
            int i = e + 16 + 4 * g + slot;
            nx[g] = (i < end) ? __ldg(&bkt[i]) : make_int2(0, 0);
        }
        float4 r[4];
        #pragma unroll
        for (int g = 0; g < 4; g++)
            r[g] = __ldg(&x[(size_t)ed[g].x * 8 + sub]);
        #pragma unroll
        for (int g = 0; g < 4; g++) {
            float w = __int_as_float(ed[g].y);
            const __half2* h = (const __half2*)&r[g];
            #pragma unroll
            for (int k = 0; k < 4; k++) {
                float2 f = __half22float2(h[k]);
                a[2 * k]     = fmaf(w, f.x, a[2 * k]);
                a[2 * k + 1] = fmaf(w, f.y, a[2 * k + 1]);
            }
        }
        #pragma unroll
        for (int g = 0; g < 4; g++) ed[g] = nx[g];
    }

    #pragma unroll
    for (int g = 0; g < 4; g++) {
        if (e + 4 * g < end) {
            float4 r = __ldg(&x[(size_t)ed[g].x * 8 + sub]);
            float w = __int_as_float(ed[g].y);
            const __half2* h = (const __half2*)&r;
            #pragma unroll
            for (int k = 0; k < 4; k++) {
                float2 f = __half22float2(h[k]);
                a[2 * k]     = fmaf(w, f.x, a[2 * k]);
                a[2 * k + 1] = fmaf(w, f.y, a[2 * k + 1]);
            }
        }
    }

    #pragma unroll
    for (int k = 0; k < 8; k++) {
        a[k] += __shfl_xor_sync(0xffffffffu, a[k], 8);
        a[k] += __shfl_xor_sync(0xffffffffu, a[k], 16);
    }
}

// ---------------- SpMM passes ----------------
template <bool NORM, bool WX, bool FINAL>
__global__ void __launch_bounds__(256) k_spmm(int gsel, int xsel, int ysel,
                                              float* out,
                                              const float* __restrict__ Gu,
                                              const float* __restrict__ Gi,
                                              int nrows) {
    int row = blockIdx.x * 8 + (threadIdx.x >> 5);
    if (row >= nrows) return;
    int lane = threadIdx.x & 31;
    int slot = lane >> 3;
    int sub  = lane & 7;

    const int*  cnt = gsel ? g_ii_cnt : g_ui_cnt;
    const int2* bkt = gsel ? g_ii_bkt : g_ui_bkt;
    const float4* x = (xsel == 0) ? g_eh0 : (xsel == 1) ? g_eh1
                    : (xsel == 2) ? g_gh0 : g_gh1;
    float4* y = (ysel == 0) ? g_eh0 : (ysel == 1) ? g_eh1
              : (ysel == 2) ? g_gh0 : g_gh1;

    float a[8];
    gather_row(cnt, bkt, x, row, slot, sub, a);

    if (NORM) {
        float ssum = 0.f;
        #pragma unroll
        for (int k = 0; k < 8; k++) ssum = fmaf(a[k], a[k], ssum);
        #pragma unroll
        for (int o = 4; o; o >>= 1) ssum += __shfl_xor_sync(0xffffffffu, ssum, o);
        float scale = 1.f / fmaxf(sqrtf(ssum), EPS_F);
        #pragma unroll
        for (int k = 0; k < 8; k++) a[k] *= scale;
    }

    if (WX && slot == 0) {
        __half2 hp[4];
        #pragma unroll
        for (int k = 0; k < 4; k++)
            hp[k] = __float22half2_rn(make_float2(a[2 * k], a[2 * k + 1]));
        y[(size_t)row * 8 + sub] = *(const float4*)hp;
    }

    if (FINAL && slot < 2) {
        size_t p = (size_t)row * 16 + 2 * sub + slot;
        float4 o = (row < U_N) ? ((const float4*)Gu)[p]
                               : ((const float4*)Gi)[(size_t)(row - U_N) * 16 + 2 * sub + slot];
        float2 p1 = ((const float2*)g_eh1)[p];
        float2 p2 = ((const float2*)g_eh0)[p];
        const __half2* h1 = (const __half2*)&p1;
        const __half2* h2 = (const __half2*)&p2;
        float2 n1a = __half22float2(h1[0]), n1b = __half22float2(h1[1]);
        float2 n2a = __half22float2(h2[0]), n2b = __half22float2(h2[1]);
        o.x = 0.25f * (o.x + n1a.x + n2a.x + a[4 * slot + 0]);
        o.y = 0.25f * (o.y + n1a.y + n2a.y + a[4 * slot + 1]);
        o.z = 0.25f * (o.z + n1b.x + n2b.x + a[4 * slot + 2]);
        o.w = 0.25f * (o.w + n1b.y + n2b.y + a[4 * slot + 3]);
        if (row >= U_N) {
            float2 gp = ((const float2*)g_gh0)[(size_t)(row - U_N) * 16 + 2 * sub + slot];
            const __half2* gh = (const __half2*)&gp;
            float2 f0 = __half22float2(gh[0]);
            float2 f1 = __half22float2(gh[1]);
            float ssum = f0.x * f0.x + f0.y * f0.y + f1.x * f1.x + f1.y * f1.y;
            #pragma unroll
            for (int o2 = 8; o2; o2 >>= 1)
                ssum += __shfl_xor_sync(0xffffffffu, ssum, o2);
            float sc = 1.f / fmaxf(sqrtf(ssum), EPS_F);
            o.x = fmaf(f0.x, sc, o.x);
            o.y = fmaf(f0.y, sc, o.y);
            o.z = fmaf(f1.x, sc, o.z);
            o.w = fmaf(f1.y, sc, o.w);
        }
        ((float4*)out)[p] = o;
    }
}

// ---------------- launch: fork II chain onto a side stream -----------------
extern "C" void kernel_launch(void* const* d_in, const int* in_sizes, int n_in,
                              void* d_out, int out_size) {
    const float* Gu     = (const float*)d_in[0];
    const float* Gi     = (const float*)d_in[1];
    const float* Gis    = (const float*)d_in[2];
    const float* ii_w   = (const float*)d_in[3];
    const float* ui_w   = (const float*)d_in[4];
    const int*   ii_src = (const int*)d_in[5];
    const int*   ii_dst = (const int*)d_in[6];
    const int*   ui_src = (const int*)d_in[7];
    const int*   ui_dst = (const int*)d_in[8];
    float* out = (float*)d_out;

    int blk_ii = (I_N + 7) / 8;
    int blk_ui = (NUI + 7) / 8;

    cudaStream_t s0 = 0;   // capture/default stream
    cudaStream_t s2;
    cudaEvent_t  eF, e2;
    bool forked = (cudaStreamCreateWithFlags(&s2, cudaStreamNonBlocking) == cudaSuccess) &&
                  (cudaEventCreateWithFlags(&eF, cudaEventDisableTiming) == cudaSuccess) &&
                  (cudaEventCreateWithFlags(&e2, cudaEventDisableTiming) == cudaSuccess);

    // Build phase (main stream)
    k_init<<<2048, 256, 0, s0>>>(Gu, Gi, Gis);
    k_fill<<<4096, 256, 0, s0>>>(ui_src, ui_dst, ui_w, ii_src, ii_dst, ii_w);

    if (forked) {
        cudaEventRecord(eF, s0);
        cudaStreamWaitEvent(s2, eF, 0);
        // II chain on side stream (independent of UI L1/L2)
        k_spmm<false, true, false><<<blk_ii, 256, 0, s2>>>(1, 2, 3, nullptr, nullptr, nullptr, I_N);
        k_spmm<false, true, false><<<blk_ii, 256, 0, s2>>>(1, 3, 2, nullptr, nullptr, nullptr, I_N);
        cudaEventRecord(e2, s2);

        // UI chain on main stream
        k_spmm<true, true, false><<<blk_ui, 256, 0, s0>>>(0, 0, 1, nullptr, nullptr, nullptr, NUI);
        k_spmm<true, true, false><<<blk_ui, 256, 0, s0>>>(0, 1, 0, nullptr, nullptr, nullptr, NUI);

        // join: UI-L3/final needs gh0 (II output)
        cudaStreamWaitEvent(s0, e2, 0);
        k_spmm<true, false, true><<<blk_ui, 256, 0, s0>>>(0, 0, 1, out, Gu, Gi, NUI);

        cudaEventDestroy(eF);
        cudaEventDestroy(e2);
        cudaStreamDestroy(s2);
    } else {
        // fallback: serial (R14 schedule)
        k_spmm<false, true, false><<<blk_ii, 256, 0, s0>>>(1, 2, 3, nullptr, nullptr, nullptr, I_N);
        k_spmm<false, true, false><<<blk_ii, 256, 0, s0>>>(1, 3, 2, nullptr, nullptr, nullptr, I_N);
        k_spmm<true, true, false><<<blk_ui, 256, 0, s0>>>(0, 0, 1, nullptr, nullptr, nullptr, NUI);
        k_spmm<true, true, false><<<blk_ui, 256, 0, s0>>>(0, 1, 0, nullptr, nullptr, nullptr, NUI);
        k_spmm<true, false, true><<<blk_ui, 256, 0, s0>>>(0, 0, 1, out, Gu, Gi, NUI);
    }
}

// round 17
// speedup vs baseline: 1.0125x; 1.0080x over previous
#include <cuda_runtime.h>
#include <cuda_fp16.h>

#define U_N   100000
#define I_N   50000
#define NUI   150000
#define KDIM  64
#define E_II  1600000
#define E_UI  4800000
#define EPS_F 1e-12f
#define SLOTS 128           // fixed bucket capacity per destination (deg ~ Poisson(32))

// ---------------- static device scratch (allocation-free) ----------------
__device__ int2  g_ui_bkt[(long long)NUI * SLOTS];   // 153.6 MB
__device__ int2  g_ii_bkt[(long long)I_N * SLOTS];   //  51.2 MB
__device__ int   g_ui_cnt[NUI];
__device__ int   g_ii_cnt[I_N];

// fp16 propagation buffers; float4-typed for 16B alignment. Row = 128B = 8 float4.
__device__ float4 g_eh0[NUI * 8];
__device__ float4 g_eh1[NUI * 8];
__device__ float4 g_gh0[I_N * 8];
__device__ float4 g_gh1[I_N * 8];

// ---------------- pre: zero counters + fp16 copies of ego / Gis ------------
__global__ void __launch_bounds__(256) k_pre(const float* __restrict__ Gu,
                                             const float* __restrict__ Gi,
                                             const float* __restrict__ Gis) {
    const int stride = gridDim.x * blockDim.x;
    int gtid = blockIdx.x * blockDim.x + threadIdx.x;

    for (int i = gtid; i < NUI; i += stride) {
        g_ui_cnt[i] = 0;
        if (i < I_N) g_ii_cnt[i] = 0;
    }

    const int n1  = NUI * 16;          // float4 elements of ego
    const int nGu = U_N * 16;
    const int tot = n1 + I_N * 16;
    for (int i = gtid; i < tot; i += stride) {
        float4 v;
        __half2* dst;
        if (i < n1) {
            v = (i < nGu) ? __ldcs(&((const float4*)Gu)[i])
                          : __ldcs(&((const float4*)Gi)[i - nGu]);
            dst = (__half2*)g_eh0 + (size_t)i * 2;
        } else {
            v = __ldcs(&((const float4*)Gis)[i - n1]);
            dst = (__half2*)g_gh0 + (size_t)(i - n1) * 2;
        }
        __half2 h0 = __float22half2_rn(make_float2(v.x, v.y));
        __half2 h1 = __float22half2_rn(make_float2(v.z, v.w));
        *(uint2*)dst = make_uint2(*(unsigned*)&h0, *(unsigned*)&h1);
    }
}

// ---------------- bucketed fills (split by graph) --------------------------
__global__ void __launch_bounds__(256) k_fill_ii(const int* __restrict__ ii_src,
                                                 const int* __restrict__ ii_dst,
                                                 const float* __restrict__ ii_w) {
    const int stride4 = gridDim.x * blockDim.x * 4;
    for (int e = (blockIdx.x * blockDim.x + threadIdx.x) * 4; e < E_II; e += stride4) {
        int4   d  = __ldcs((const int4*)(ii_dst + e));
        int4   sr = __ldcs((const int4*)(ii_src + e));
        float4 wv = __ldcs((const float4*)(ii_w + e));
        int p;
        p = atomicAdd(&g_ii_cnt[d.x], 1);
        if (p < SLOTS) g_ii_bkt[(size_t)d.x * SLOTS + p] = make_int2(sr.x, __float_as_int(wv.x));
        p = atomicAdd(&g_ii_cnt[d.y], 1);
        if (p < SLOTS) g_ii_bkt[(size_t)d.y * SLOTS + p] = make_int2(sr.y, __float_as_int(wv.y));
        p = atomicAdd(&g_ii_cnt[d.z], 1);
        if (p < SLOTS) g_ii_bkt[(size_t)d.z * SLOTS + p] = make_int2(sr.z, __float_as_int(wv.z));
        p = atomicAdd(&g_ii_cnt[d.w], 1);
        if (p < SLOTS) g_ii_bkt[(size_t)d.w * SLOTS + p] = make_int2(sr.w, __float_as_int(wv.w));
    }
}

__global__ void __launch_bounds__(256) k_fill_ui(const int* __restrict__ ui_src,
                                                 const int* __restrict__ ui_dst,
                                                 const float* __restrict__ ui_w) {
    const int stride4 = gridDim.x * blockDim.x * 4;
    for (int e = (blockIdx.x * blockDim.x + threadIdx.x) * 4; e < E_UI; e += stride4) {
        int4   d  = __ldcs((const int4*)(ui_dst + e));
        int4   sr = __ldcs((const int4*)(ui_src + e));
        float4 wv = __ldcs((const float4*)(ui_w + e));
        int p;
        p = atomicAdd(&g_ui_cnt[d.x], 1);
        if (p < SLOTS) g_ui_bkt[(size_t)d.x * SLOTS + p] = make_int2(sr.x, __float_as_int(wv.x));
        p = atomicAdd(&g_ui_cnt[d.y], 1);
        if (p < SLOTS) g_ui_bkt[(size_t)d.y * SLOTS + p] = make_int2(sr.y, __float_as_int(wv.y));
        p = atomicAdd(&g_ui_cnt[d.z], 1);
        if (p < SLOTS) g_ui_bkt[(size_t)d.z * SLOTS + p] = make_int2(sr.z, __float_as_int(wv.z));
        p = atomicAdd(&g_ui_cnt[d.w], 1);
        if (p < SLOTS) g_ui_bkt[(size_t)d.w * SLOTS + p] = make_int2(sr.w, __float_as_int(wv.w));
    }
}

// ---------------- gather core (exact R14/R8 loop) --------------------------
// 4 edge-slots x 8 lanes, 16-edge pipeline, 4 gathers in flight.
__device__ __forceinline__ void gather_row(const int* __restrict__ cnt,
                                           const int2* __restrict__ bkt,
                                           const float4* __restrict__ x,
                                           int row, int slot, int sub,
                                           float a[8]) {
    int beg = row * SLOTS;
    int n   = cnt[row];
    if (n > SLOTS) n = SLOTS;
    int end = beg + n;
    #pragma unroll
    for (int k = 0; k < 8; k++) a[k] = 0.f;

    int2 ed[4];
    #pragma unroll
    for (int g = 0; g < 4; g++) {
        int i = beg + 4 * g + slot;
        ed[g] = (i < end) ? __ldg(&bkt[i]) : make_int2(0, 0);
    }

    int e = beg;
    for (; e + 16 <= end; e += 16) {
        int2 nx[4];
        #pragma unroll
        for (int g = 0; g < 4; g++) {
            int i = e + 16 + 4 * g + slot;
            nx[g] = (i < end) ? __ldg(&bkt[i]) : make_int2(0, 0);
        }
        float4 r[4];
        #pragma unroll
        for (int g = 0; g < 4; g++)
            r[g] = __ldg(&x[(size_t)ed[g].x * 8 + sub]);
        #pragma unroll
        for (int g = 0; g < 4; g++) {
            float w = __int_as_float(ed[g].y);
            const __half2* h = (const __half2*)&r[g];
            #pragma unroll
            for (int k = 0; k < 4; k++) {
                float2 f = __half22float2(h[k]);
                a[2 * k]     = fmaf(w, f.x, a[2 * k]);
                a[2 * k + 1] = fmaf(w, f.y, a[2 * k + 1]);
            }
        }
        #pragma unroll
        for (int g = 0; g < 4; g++) ed[g] = nx[g];
    }

    #pragma unroll
    for (int g = 0; g < 4; g++) {
        if (e + 4 * g < end) {
            float4 r = __ldg(&x[(size_t)ed[g].x * 8 + sub]);
            float w = __int_as_float(ed[g].y);
            const __half2* h = (const __half2*)&r;
            #pragma unroll
            for (int k = 0; k < 4; k++) {
                float2 f = __half22float2(h[k]);
                a[2 * k]     = fmaf(w, f.x, a[2 * k]);
                a[2 * k + 1] = fmaf(w, f.y, a[2 * k + 1]);
            }
        }
    }

    #pragma unroll
    for (int k = 0; k < 8; k++) {
        a[k] += __shfl_xor_sync(0xffffffffu, a[k], 8);
        a[k] += __shfl_xor_sync(0xffffffffu, a[k], 16);
    }
}

// ---------------- SpMM passes ----------------
template <bool NORM, bool WX, bool FINAL>
__global__ void __launch_bounds__(256) k_spmm(int gsel, int xsel, int ysel,
                                              float* out,
                                              const float* __restrict__ Gu,
                                              const float* __restrict__ Gi,
                                              int nrows) {
    int row = blockIdx.x * 8 + (threadIdx.x >> 5);
    if (row >= nrows) return;
    int lane = threadIdx.x & 31;
    int slot = lane >> 3;
    int sub  = lane & 7;

    const int*  cnt = gsel ? g_ii_cnt : g_ui_cnt;
    const int2* bkt = gsel ? g_ii_bkt : g_ui_bkt;
    const float4* x = (xsel == 0) ? g_eh0 : (xsel == 1) ? g_eh1
                    : (xsel == 2) ? g_gh0 : g_gh1;
    float4* y = (ysel == 0) ? g_eh0 : (ysel == 1) ? g_eh1
              : (ysel == 2) ? g_gh0 : g_gh1;

    float a[8];
    gather_row(cnt, bkt, x, row, slot, sub, a);

    if (NORM) {
        float ssum = 0.f;
        #pragma unroll
        for (int k = 0; k < 8; k++) ssum = fmaf(a[k], a[k], ssum);
        #pragma unroll
        for (int o = 4; o; o >>= 1) ssum += __shfl_xor_sync(0xffffffffu, ssum, o);
        float scale = 1.f / fmaxf(sqrtf(ssum), EPS_F);
        #pragma unroll
        for (int k = 0; k < 8; k++) a[k] *= scale;
    }

    if (WX && slot == 0) {
        __half2 hp[4];
        #pragma unroll
        for (int k = 0; k < 4; k++)
            hp[k] = __float22half2_rn(make_float2(a[2 * k], a[2 * k + 1]));
        y[(size_t)row * 8 + sub] = *(const float4*)hp;
    }

    if (FINAL && slot < 2) {
        size_t p = (size_t)row * 16 + 2 * sub + slot;
        float4 o = (row < U_N) ? ((const float4*)Gu)[p]
                               : ((const float4*)Gi)[(size_t)(row - U_N) * 16 + 2 * sub + slot];
        float2 p1 = ((const float2*)g_eh1)[p];
        float2 p2 = ((const float2*)g_eh0)[p];
        const __half2* h1 = (const __half2*)&p1;
        const __half2* h2 = (const __half2*)&p2;
        float2 n1a = __half22float2(h1[0]), n1b = __half22float2(h1[1]);
        float2 n2a = __half22float2(h2[0]), n2b = __half22float2(h2[1]);
        o.x = 0.25f * (o.x + n1a.x + n2a.x + a[4 * slot + 0]);
        o.y = 0.25f * (o.y + n1a.y + n2a.y + a[4 * slot + 1]);
        o.z = 0.25f * (o.z + n1b.x + n2b.x + a[4 * slot + 2]);
        o.w = 0.25f * (o.w + n1b.y + n2b.y + a[4 * slot + 3]);
        if (row >= U_N) {
            float2 gp = ((const float2*)g_gh0)[(size_t)(row - U_N) * 16 + 2 * sub + slot];
            const __half2* gh = (const __half2*)&gp;
            float2 f0 = __half22float2(gh[0]);
            float2 f1 = __half22float2(gh[1]);
            float ssum = f0.x * f0.x + f0.y * f0.y + f1.x * f1.x + f1.y * f1.y;
            #pragma unroll
            for (int o2 = 8; o2; o2 >>= 1)
                ssum += __shfl_xor_sync(0xffffffffu, ssum, o2);
            float sc = 1.f / fmaxf(sqrtf(ssum), EPS_F);
            o.x = fmaf(f0.x, sc, o.x);
            o.y = fmaf(f0.y, sc, o.y);
            o.z = fmaf(f1.x, sc, o.z);
            o.w = fmaf(f1.y, sc, o.w);
        }
        ((float4*)out)[p] = o;
    }
}

// ---------------- launch: II chain overlapped with UI fill -----------------
extern "C" void kernel_launch(void* const* d_in, const int* in_sizes, int n_in,
                              void* d_out, int out_size) {
    const float* Gu     = (const float*)d_in[0];
    const float* Gi     = (const float*)d_in[1];
    const float* Gis    = (const float*)d_in[2];
    const float* ii_w   = (const float*)d_in[3];
    const float* ui_w   = (const float*)d_in[4];
    const int*   ii_src = (const int*)d_in[5];
    const int*   ii_dst = (const int*)d_in[6];
    const int*   ui_src = (const int*)d_in[7];
    const int*   ui_dst = (const int*)d_in[8];
    float* out = (float*)d_out;

    int blk_ii = (I_N + 7) / 8;
    int blk_ui = (NUI + 7) / 8;

    cudaStream_t s0 = 0;
    cudaStream_t s2;
    cudaEvent_t  eII, e2;
    bool forked = (cudaStreamCreateWithFlags(&s2, cudaStreamNonBlocking) == cudaSuccess) &&
                  (cudaEventCreateWithFlags(&eII, cudaEventDisableTiming) == cudaSuccess) &&
                  (cudaEventCreateWithFlags(&e2, cudaEventDisableTiming) == cudaSuccess);

    k_pre<<<2048, 256, 0, s0>>>(Gu, Gi, Gis);
    k_fill_ii<<<1600, 256, 0, s0>>>(ii_src, ii_dst, ii_w);

    if (forked) {
        cudaEventRecord(eII, s0);
        cudaStreamWaitEvent(s2, eII, 0);
        // II chain on side stream — overlaps fill_ui + UI-L1 head on s0
        k_spmm<false, true, false><<<blk_ii, 256, 0, s2>>>(1, 2, 3, nullptr, nullptr, nullptr, I_N);
        k_spmm<false, true, false><<<blk_ii, 256, 0, s2>>>(1, 3, 2, nullptr, nullptr, nullptr, I_N);
        cudaEventRecord(e2, s2);

        k_fill_ui<<<4096, 256, 0, s0>>>(ui_src, ui_dst, ui_w);
        k_spmm<true, true, false><<<blk_ui, 256, 0, s0>>>(0, 0, 1, nullptr, nullptr, nullptr, NUI);
        k_spmm<true, true, false><<<blk_ui, 256, 0, s0>>>(0, 1, 0, nullptr, nullptr, nullptr, NUI);

        cudaStreamWaitEvent(s0, e2, 0);
        k_spmm<true, false, true><<<blk_ui, 256, 0, s0>>>(0, 0, 1, out, Gu, Gi, NUI);

        cudaEventDestroy(eII);
        cudaEventDestroy(e2);
        cudaStreamDestroy(s2);
    } else {
        k_fill_ui<<<4096, 256, 0, s0>>>(ui_src, ui_dst, ui_w);
        k_spmm<false, true, false><<<blk_ii, 256, 0, s0>>>(1, 2, 3, nullptr, nullptr, nullptr, I_N);
        k_spmm<false, true, false><<<blk_ii, 256, 0, s0>>>(1, 3, 2, nullptr, nullptr, nullptr, I_N);
        k_spmm<true, true, false><<<blk_ui, 256, 0, s0>>>(0, 0, 1, nullptr, nullptr, nullptr, NUI);
        k_spmm<true, true, false><<<blk_ui, 256, 0, s0>>>(0, 1, 0, nullptr, nullptr, nullptr, NUI);
        k_spmm<true, false, true><<<blk_ui, 256, 0, s0>>>(0, 0, 1, out, Gu, Gi, NUI);
    }
}